// round 10
// baseline (speedup 1.0000x reference)
#include <cuda_runtime.h>
#include <cuda_bf16.h>
#include <cstdint>
#include <cstddef>

// CCLayer via HMMA bf16 (hi/lo split x3). TILE=32, 256 thr, 3 CTAs/SM.
//   D1[j,p] = Z_tile^T @ U ; w = (alpha - D1).*Pi ; s = colsum(Pi)
//   D2[j,d] = w @ U^T ; out[0:256] = z*s + D2 ; out[256:288] = Pi
#define DD 256
#define PP 32
#define TILE 32
#define THREADS 256

#define U1_STR 528           // U1[p][d] bf16 rows (conflict-free for LDS32 pattern)
#define D1_STR 140           // D1 rows: 35 words, gcd(35,32)=1
#define W_STR  84            // W[j][p] bf16 rows

// ---- persistent smem (bytes) ----
// A: 256 rows x 128B; row d = [32 x hi bf16 (64B) | 32 x lo bf16 (64B)],
// 16B-chunk XOR swizzle ((d&7)<<4).
#define OFF_A      0         // 32768
#define OFF_U1H    32768     // 32*528 = 16896
#define OFF_U1L    49664
#define OFF_ALPHA  66560     // 32 f32
#define OFF_SPART  66688     // 8*32 f32 = 1024
#define SMEM_BYTES 67712

// ---- aliases inside A region (A dead after GEMM1) ----
#define OFF_D1     0         // 4 * 32*140 = 17920
#define D1_KH      4480
#define OFF_W_HI   17920     // 32*84 = 2688
#define OFF_W_LO   20608     // ends 23296 < 32768

#define MMA_BF16(d, a0, a1, a2, a3, b0, b1)                                  \
    asm volatile(                                                            \
        "mma.sync.aligned.m16n8k16.row.col.f32.bf16.bf16.f32 "               \
        "{%0,%1,%2,%3}, {%4,%5,%6,%7}, {%8,%9}, {%0,%1,%2,%3};"              \
        : "+f"(d[0]), "+f"(d[1]), "+f"(d[2]), "+f"(d[3])                     \
        : "r"(a0), "r"(a1), "r"(a2), "r"(a3), "r"(b0), "r"(b1))

#define LDSM_T4(r0, r1, r2, r3, addr)                                        \
    asm volatile(                                                            \
        "ldmatrix.sync.aligned.m8n8.x4.trans.shared.b16 {%0,%1,%2,%3}, [%4];"\
        : "=r"(r0), "=r"(r1), "=r"(r2), "=r"(r3) : "r"(addr))

#define LDS32(r, addr) \
    asm volatile("ld.shared.b32 %0, [%1];" : "=r"(r) : "r"(addr))
#define LDSF(r, addr) \
    asm volatile("ld.shared.f32 %0, [%1];" : "=f"(r) : "r"(addr))
#define STS32(addr, v) \
    asm volatile("st.shared.b32 [%0], %1;" :: "r"(addr), "r"(v) : "memory")
#define STS16(addr, v) \
    asm volatile("st.shared.u16 [%0], %1;" :: "r"(addr), "h"(v) : "memory")
#define STSF(addr, v) \
    asm volatile("st.shared.f32 [%0], %1;" :: "r"(addr), "f"(v) : "memory")

__device__ __forceinline__ uint32_t pack_hi2(float a, float b) {
    __nv_bfloat16 ha = __float2bfloat16_rn(a);
    __nv_bfloat16 hb = __float2bfloat16_rn(b);
    return (uint32_t)__bfloat16_as_ushort(ha) |
           ((uint32_t)__bfloat16_as_ushort(hb) << 16);
}
__device__ __forceinline__ uint32_t pack_lo2(float a, float b) {
    __nv_bfloat16 ha = __float2bfloat16_rn(a);
    __nv_bfloat16 hb = __float2bfloat16_rn(b);
    float ra = a - __bfloat162float(ha);
    float rb = b - __bfloat162float(hb);
    return (uint32_t)__bfloat16_as_ushort(__float2bfloat16_rn(ra)) |
           ((uint32_t)__bfloat16_as_ushort(__float2bfloat16_rn(rb)) << 16);
}

__global__ __launch_bounds__(THREADS, 3)
void cclayer_mma4(const float* __restrict__ ZPi,
                  const float* __restrict__ U,
                  const float* __restrict__ alpha,
                  float* __restrict__ out,
                  int N, int ntiles) {
    extern __shared__ __align__(128) char smem[];
    uint32_t sbase;
    asm("{ .reg .u64 t; cvta.to.shared.u64 t, %1; cvt.u32.u64 %0, t; }"
        : "=r"(sbase) : "l"(smem));

    const int tid = threadIdx.x;
    const int warp = tid >> 5;
    const int lane = tid & 31;
    const size_t sN = (size_t)N;

    // ---- persistent: U1[p][d] hi/lo, alpha ----
    for (int i = tid; i < DD * PP; i += THREADS) {
        const int d = i >> 5, p = i & 31;
        const float v = U[i];
        const __nv_bfloat16 h = __float2bfloat16_rn(v);
        const __nv_bfloat16 l = __float2bfloat16_rn(v - __bfloat162float(h));
        *(uint16_t*)(smem + OFF_U1H + p * U1_STR + d * 2) = __bfloat16_as_ushort(h);
        *(uint16_t*)(smem + OFF_U1L + p * U1_STR + d * 2) = __bfloat16_as_ushort(l);
    }
    if (tid < PP) ((float*)(smem + OFF_ALPHA))[tid] = alpha[tid];
    __syncthreads();

    const float* __restrict__ sAlpha = (const float*)(smem + OFF_ALPHA);
    float* __restrict__ sPart = (float*)(smem + OFF_SPART);

    // GEMM1 decode: warp = jh(2) + 2*kq(4)
    const int jh = warp & 1;
    const int kq = warp >> 1;
    const int krow_l = (lane & 7) + ((lane >> 4) & 1) * 8;
    const int jcolb = jh * 32 + ((lane >> 3) & 1) * 16;   // byte offset in hi half
    const uint32_t b1off = (uint32_t)((lane >> 2) * U1_STR + (lane & 3) * 4);
    // GEMM2 decode: warp = jblk(2) + 2*dq(4)
    const int jblk = (warp & 1) * 16;
    const int dq = warp >> 1;
    const uint32_t wOffA = (uint32_t)((jblk + (lane >> 2)) * W_STR + (lane & 3) * 4);
    const int p_l = (lane & 7) + ((lane >> 3) & 1) * 8;
    const int dcol_l = ((lane >> 4) & 1) * 8;
    const int j1 = jblk + (lane >> 2);
    // epi1/Pi mapping
    const int jj = tid & 31;
    const int pg = tid >> 5;            // 0..7, 4 p's each
    const int p0g = pg * 4;

    for (int t = blockIdx.x; t < ntiles; t += gridDim.x) {
        const int col0 = t * TILE;

        // ===== phase 1: Z tile -> A (packed hi|lo rows, swizzled) =====
#pragma unroll 4
        for (int i = 0; i < 32; i++) {
            const int d = warp * 32 + i;
            const float v = ZPi[(size_t)d * sN + col0 + lane];
            const __nv_bfloat16 h = __float2bfloat16_rn(v);
            const __nv_bfloat16 l = __float2bfloat16_rn(v - __bfloat162float(h));
            const uint32_t sw = (uint32_t)((d & 7) << 4);
            const uint32_t row = (uint32_t)(d * 128 + lane * 2);
            STS16(sbase + OFF_A + (row ^ sw), __bfloat16_as_ushort(h));
            STS16(sbase + OFF_A + ((row + 64) ^ sw), __bfloat16_as_ushort(l));
        }

        // ---- early Pi: regs + pass-through + partial s ----
        float piR[4];
        {
            float sacc = 0.f;
            const size_t c = (size_t)col0 + jj;
#pragma unroll
            for (int i = 0; i < 4; i++) {
                const size_t off = (size_t)(DD + p0g + i) * sN + c;
                piR[i] = ZPi[off];
                out[off] = piR[i];
                sacc += piR[i];
            }
            sPart[pg * 32 + jj] = sacc;
        }
        __syncthreads();

        // ===== GEMM1: D1[j,p] partials, k-split 4 =====
        float d1[4][4];
#pragma unroll
        for (int nt = 0; nt < 4; nt++)
#pragma unroll
            for (int q = 0; q < 4; q++) d1[nt][q] = 0.f;

#pragma unroll
        for (int ks = 0; ks < 4; ks++) {
            const int dbase = kq * 64 + ks * 16;
            const int d_l = dbase + krow_l;
            const uint32_t sw = (uint32_t)((d_l & 7) << 4);
            const uint32_t rowb = (uint32_t)(d_l * 128);
            uint32_t ah0, ah1, ah2, ah3, al0, al1, al2, al3;
            LDSM_T4(ah0, ah1, ah2, ah3, sbase + OFF_A + ((rowb + jcolb) ^ sw));
            LDSM_T4(al0, al1, al2, al3, sbase + OFF_A + ((rowb + 64 + jcolb) ^ sw));
            const uint32_t bh_base = sbase + OFF_U1H + b1off + dbase * 2;
            const uint32_t bl_base = sbase + OFF_U1L + b1off + dbase * 2;
#pragma unroll
            for (int nt = 0; nt < 4; nt++) {
                uint32_t bh0, bh1, bl0, bl1;
                LDS32(bh0, bh_base + nt * 8 * U1_STR);
                LDS32(bh1, bh_base + nt * 8 * U1_STR + 16);
                LDS32(bl0, bl_base + nt * 8 * U1_STR);
                LDS32(bl1, bl_base + nt * 8 * U1_STR + 16);
                MMA_BF16(d1[nt], ah0, ah1, ah2, ah3, bh0, bh1);
                MMA_BF16(d1[nt], ah0, ah1, ah2, ah3, bl0, bl1);
                MMA_BF16(d1[nt], al0, al1, al2, al3, bh0, bh1);
            }
        }
        __syncthreads();   // all A reads done before aliased D1/W writes

        // ---- store D1 partials [kq][j][p] ----
        {
            const uint32_t base = sbase + OFF_D1 + kq * D1_KH;
            const int jr = jh * 16 + (lane >> 2);   // wait: jh*16? j-blocks are 16 wide
#pragma unroll
            for (int nt = 0; nt < 4; nt++) {
                const int p = nt * 8 + 2 * (lane & 3);
                const uint32_t a0 = base + jr * D1_STR + p * 4;
                const uint32_t a1 = base + (jr + 8) * D1_STR + p * 4;
                STSF(a0, d1[nt][0]);
                STSF(a0 + 4, d1[nt][1]);
                STSF(a1, d1[nt][2]);
                STSF(a1 + 4, d1[nt][3]);
            }
        }
        __syncthreads();

        // ===== epilogue 1: w from D1 + reg Pi =====
        {
            const uint32_t db = sbase + OFF_D1 + jj * D1_STR;
            float wv[4];
#pragma unroll
            for (int i = 0; i < 4; i++) {
                const int p = p0g + i;
                float x0, x1, x2, x3;
                LDSF(x0, db + p * 4);
                LDSF(x1, db + D1_KH + p * 4);
                LDSF(x2, db + 2 * D1_KH + p * 4);
                LDSF(x3, db + 3 * D1_KH + p * 4);
                wv[i] = (sAlpha[p] - ((x0 + x1) + (x2 + x3))) * piR[i];
            }
            const uint32_t wa = sbase + (uint32_t)(jj * W_STR + p0g * 2);
            STS32(wa + OFF_W_HI, pack_hi2(wv[0], wv[1]));
            STS32(wa + OFF_W_LO, pack_lo2(wv[0], wv[1]));
            STS32(wa + OFF_W_HI + 4, pack_hi2(wv[2], wv[3]));
            STS32(wa + OFF_W_LO + 4, pack_lo2(wv[2], wv[3]));
        }
        __syncthreads();

        // ===== GEMM2 + fused epilogue 2 =====
        float s1 = 0.f, s2 = 0.f;
#pragma unroll
        for (int gq = 0; gq < 8; gq++) {
            s1 += sPart[gq * 32 + j1];
            s2 += sPart[gq * 32 + j1 + 8];
        }

#pragma unroll 1
        for (int h = 0; h < 2; h++) {          // two 32-d halves of the quarter
            // preload epilogue Z values (L2/L1-resident) before the MMAs
            float zr[4][4];
            const size_t c1 = (size_t)col0 + j1;
#pragma unroll
            for (int nt = 0; nt < 4; nt++) {
                const int d0 = dq * 64 + h * 32 + nt * 8 + 2 * (lane & 3);
                const size_t o00 = (size_t)d0 * sN + c1;
                const size_t o01 = (size_t)(d0 + 1) * sN + c1;
                zr[nt][0] = ZPi[o00];
                zr[nt][1] = ZPi[o01];
                zr[nt][2] = ZPi[o00 + 8];
                zr[nt][3] = ZPi[o01 + 8];
            }

            float d2[4][4];
#pragma unroll
            for (int nt = 0; nt < 4; nt++)
#pragma unroll
                for (int q = 0; q < 4; q++) d2[nt][q] = 0.f;

#pragma unroll
            for (int ks = 0; ks < 2; ks++) {
                uint32_t ah0, ah1, ah2, ah3, al0, al1, al2, al3;
                const uint32_t wh = sbase + OFF_W_HI + wOffA + ks * 32;
                const uint32_t wl = sbase + OFF_W_LO + wOffA + ks * 32;
                LDS32(ah0, wh);
                LDS32(ah1, wh + 8 * W_STR);
                LDS32(ah2, wh + 16);
                LDS32(ah3, wh + 8 * W_STR + 16);
                LDS32(al0, wl);
                LDS32(al1, wl + 8 * W_STR);
                LDS32(al2, wl + 16);
                LDS32(al3, wl + 8 * W_STR + 16);
#pragma unroll
                for (int ntp = 0; ntp < 2; ntp++) {
                    const int d0p = dq * 64 + h * 32 + ntp * 16;
                    const uint32_t la = (uint32_t)((ks * 16 + p_l) * U1_STR +
                                                   (d0p + dcol_l) * 2);
                    uint32_t bh0, bh1, bh2, bh3, bl0, bl1, bl2, bl3;
                    LDSM_T4(bh0, bh1, bh2, bh3, sbase + OFF_U1H + la);
                    LDSM_T4(bl0, bl1, bl2, bl3, sbase + OFF_U1L + la);
                    MMA_BF16(d2[2 * ntp], ah0, ah1, ah2, ah3, bh0, bh1);
                    MMA_BF16(d2[2 * ntp], ah0, ah1, ah2, ah3, bl0, bl1);
                    MMA_BF16(d2[2 * ntp], al0, al1, al2, al3, bh0, bh1);
                    MMA_BF16(d2[2 * ntp + 1], ah0, ah1, ah2, ah3, bh2, bh3);
                    MMA_BF16(d2[2 * ntp + 1], ah0, ah1, ah2, ah3, bl2, bl3);
                    MMA_BF16(d2[2 * ntp + 1], al0, al1, al2, al3, bh2, bh3);
                }
            }

            // fused epilogue 2: out = z*s + D2
#pragma unroll
            for (int nt = 0; nt < 4; nt++) {
                const int d0 = dq * 64 + h * 32 + nt * 8 + 2 * (lane & 3);
                const size_t o00 = (size_t)d0 * sN + c1;
                const size_t o01 = (size_t)(d0 + 1) * sN + c1;
                out[o00] = fmaf(zr[nt][0], s1, d2[nt][0]);
                out[o01] = fmaf(zr[nt][1], s1, d2[nt][1]);
                out[o00 + 8] = fmaf(zr[nt][2], s2, d2[nt][2]);
                out[o01 + 8] = fmaf(zr[nt][3], s2, d2[nt][3]);
            }
        }
        __syncthreads();   // W/sPart/D1 dead before next tile's phase 1
    }
}

extern "C" void kernel_launch(void* const* d_in, const int* in_sizes, int n_in,
                              void* d_out, int out_size) {
    const float* ZPi   = (const float*)d_in[0];
    const float* U     = (const float*)d_in[1];
    const float* alpha = (const float*)d_in[2];
    float* out = (float*)d_out;

    const int N = in_sizes[0] / (DD + PP);
    const int ntiles = N / TILE;

    static int nsm = 0;
    if (nsm == 0) {
        cudaDeviceGetAttribute(&nsm, cudaDevAttrMultiProcessorCount, 0);
        cudaFuncSetAttribute(cclayer_mma4, cudaFuncAttributeMaxDynamicSharedMemorySize,
                             SMEM_BYTES);
    }
    int grid = 3 * nsm;
    if (grid > ntiles) grid = ntiles;
    cclayer_mma4<<<grid, THREADS, SMEM_BYTES>>>(ZPi, U, alpha, out, N, ntiles);
}

// round 11
// speedup vs baseline: 1.3760x; 1.3760x over previous
#include <cuda_runtime.h>
#include <cuda_bf16.h>
#include <cstdint>
#include <cstddef>

// CCLayer via HMMA bf16 (single precision level — no hi/lo split).
// TILE=64, 256 threads, 4 CTAs/SM.
//   D1[j,p] = Z_tile^T @ U ; w = (alpha - D1).*Pi ; s = colsum(Pi)
//   D2[j,d] = w @ U^T ; out[0:256] = z*s + D2 ; out[256:288] = Pi
#define DD 256
#define PP 32
#define TILE 64
#define THREADS 256

#define U1_STR 528           // U1[p][d] bf16 rows
#define D1_STR 132           // 33 words, gcd(33,32)=1 -> conflict-free epi reads
#define D1_KH  8448          // 64*132
#define W_STR  84            // W[j][p] bf16 rows

// ---- persistent smem (bytes) ----
#define OFF_A      0         // 256 rows x 128B (64 j bf16), XOR-swizzled  (32KB)
#define OFF_U1H    32768     // 32*528 = 16896
#define OFF_ALPHA  49664     // 32 f32
#define OFF_SPART  49792     // 4*64 f32 = 1024
#define SMEM_BYTES 50816

// ---- aliases inside A region (A dead after GEMM1) ----
#define OFF_D1     0         // 2*8448 = 16896
#define OFF_W      16896     // 64*84 = 5376, ends 22272 < 32768

#define MMA_BF16(d, a0, a1, a2, a3, b0, b1)                                  \
    asm volatile(                                                            \
        "mma.sync.aligned.m16n8k16.row.col.f32.bf16.bf16.f32 "               \
        "{%0,%1,%2,%3}, {%4,%5,%6,%7}, {%8,%9}, {%0,%1,%2,%3};"              \
        : "+f"(d[0]), "+f"(d[1]), "+f"(d[2]), "+f"(d[3])                     \
        : "r"(a0), "r"(a1), "r"(a2), "r"(a3), "r"(b0), "r"(b1))

#define LDSM_T4(r0, r1, r2, r3, addr)                                        \
    asm volatile(                                                            \
        "ldmatrix.sync.aligned.m8n8.x4.trans.shared.b16 {%0,%1,%2,%3}, [%4];"\
        : "=r"(r0), "=r"(r1), "=r"(r2), "=r"(r3) : "r"(addr))

#define LDS32(r, addr) \
    asm volatile("ld.shared.b32 %0, [%1];" : "=r"(r) : "r"(addr))
#define LDSF(r, addr) \
    asm volatile("ld.shared.f32 %0, [%1];" : "=f"(r) : "r"(addr))
#define STS32(addr, v) \
    asm volatile("st.shared.b32 [%0], %1;" :: "r"(addr), "r"(v) : "memory")
#define STSF(addr, v) \
    asm volatile("st.shared.f32 [%0], %1;" :: "r"(addr), "f"(v) : "memory")

__device__ __forceinline__ uint32_t pack_bf2(float a, float b) {
    return (uint32_t)__bfloat16_as_ushort(__float2bfloat16_rn(a)) |
           ((uint32_t)__bfloat16_as_ushort(__float2bfloat16_rn(b)) << 16);
}

__global__ __launch_bounds__(THREADS, 4)
void cclayer_mma5(const float* __restrict__ ZPi,
                  const float* __restrict__ U,
                  const float* __restrict__ alpha,
                  float* __restrict__ out,
                  int N, int ntiles) {
    extern __shared__ __align__(128) char smem[];
    uint32_t sbase;
    asm("{ .reg .u64 t; cvta.to.shared.u64 t, %1; cvt.u32.u64 %0, t; }"
        : "=r"(sbase) : "l"(smem));

    const int tid = threadIdx.x;
    const int warp = tid >> 5;
    const int lane = tid & 31;
    const size_t sN = (size_t)N;

    // ---- persistent: U1[p][d] bf16, alpha ----
    for (int i = tid; i < DD * PP; i += THREADS) {
        const int d = i >> 5, p = i & 31;
        *(uint16_t*)(smem + OFF_U1H + p * U1_STR + d * 2) =
            __bfloat16_as_ushort(__float2bfloat16_rn(U[i]));
    }
    if (tid < PP) ((float*)(smem + OFF_ALPHA))[tid] = alpha[tid];
    __syncthreads();

    const float* __restrict__ sAlpha = (const float*)(smem + OFF_ALPHA);
    float* __restrict__ sPart = (float*)(smem + OFF_SPART);

    // GEMM1 decode: warp = jh(4) + 4*kh(2)
    const int jh = warp & 3;
    const int kh = warp >> 2;
    const int krow_l = (lane & 7) + ((lane >> 4) & 1) * 8;
    const int jcolb = jh * 32 + ((lane >> 3) & 1) * 16;
    const uint32_t b1off = (uint32_t)((lane >> 2) * U1_STR + (lane & 3) * 4);
    // GEMM2 decode: warp = jblk(4) + 4*dh(2)
    const int jblk = (warp & 3) * 16;
    const int dh = warp >> 2;
    const uint32_t wOffA = (uint32_t)((jblk + (lane >> 2)) * W_STR + (lane & 3) * 4);
    const int p_l = (lane & 7) + ((lane >> 3) & 1) * 8;
    const int dcol_l = ((lane >> 4) & 1) * 8;
    const int j1 = jblk + (lane >> 2);
    // epi1 mapping: 4 p-groups x 64 j
    const int jj = tid & 63;
    const int pg = tid >> 6;             // 0..3, 8 p's each
    const int p0g = pg * 8;

    for (int t = blockIdx.x; t < ntiles; t += gridDim.x) {
        const int col0 = t * TILE;

        // ===== phase 1: Z tile -> A bf16 (swizzled) =====
#pragma unroll 4
        for (int i = 0; i < 32; i++) {
            const int d = warp * 32 + i;
            const float2 v = *(const float2*)(ZPi + (size_t)d * sN + col0 + 2 * lane);
            const uint32_t off = (uint32_t)(d * 128 + lane * 4) ^ (uint32_t)((d & 7) << 4);
            *(uint32_t*)(smem + OFF_A + off) = pack_bf2(v.x, v.y);
        }

        // ---- early Pi: regs + pass-through + partial s ----
        float piR[8];
        {
            float sacc = 0.f;
            const size_t c = (size_t)col0 + jj;
#pragma unroll
            for (int i = 0; i < 8; i++) {
                const size_t off = (size_t)(DD + p0g + i) * sN + c;
                piR[i] = ZPi[off];
                out[off] = piR[i];
                sacc += piR[i];
            }
            sPart[pg * 64 + jj] = sacc;
        }
        __syncthreads();

        // ===== GEMM1: D1[j,p] partials, k-split 2 =====
        float d1[4][4];
#pragma unroll
        for (int nt = 0; nt < 4; nt++)
#pragma unroll
            for (int q = 0; q < 4; q++) d1[nt][q] = 0.f;

#pragma unroll
        for (int ks = 0; ks < 8; ks++) {
            const int dbase = kh * 128 + ks * 16;
            const int d_l = dbase + krow_l;
            const uint32_t asw = (uint32_t)(d_l * 128 + jcolb) ^ (uint32_t)((d_l & 7) << 4);
            uint32_t a0, a1, a2, a3;
            LDSM_T4(a0, a1, a2, a3, sbase + OFF_A + asw);
            const uint32_t bb = sbase + OFF_U1H + b1off + dbase * 2;
#pragma unroll
            for (int nt = 0; nt < 4; nt++) {
                uint32_t b0, b1;
                LDS32(b0, bb + nt * 8 * U1_STR);
                LDS32(b1, bb + nt * 8 * U1_STR + 16);
                MMA_BF16(d1[nt], a0, a1, a2, a3, b0, b1);
            }
        }
        __syncthreads();   // all A reads done before aliased D1/W writes

        // ---- store D1 partials [kh][j][p] ----
        {
            const uint32_t base = sbase + OFF_D1 + kh * D1_KH;
            const int jr = jh * 16 + (lane >> 2);
#pragma unroll
            for (int nt = 0; nt < 4; nt++) {
                const int p = nt * 8 + 2 * (lane & 3);
                const uint32_t a0 = base + jr * D1_STR + p * 4;
                const uint32_t a1 = base + (jr + 8) * D1_STR + p * 4;
                STSF(a0, d1[nt][0]);
                STSF(a0 + 4, d1[nt][1]);
                STSF(a1, d1[nt][2]);
                STSF(a1 + 4, d1[nt][3]);
            }
        }
        __syncthreads();

        // ===== epilogue 1: w from D1 + reg Pi =====
        {
            const uint32_t db = sbase + OFF_D1 + jj * D1_STR;
            float wv[8];
#pragma unroll
            for (int i = 0; i < 8; i++) {
                const int p = p0g + i;
                float x0, x1;
                LDSF(x0, db + p * 4);
                LDSF(x1, db + D1_KH + p * 4);
                wv[i] = (sAlpha[p] - (x0 + x1)) * piR[i];
            }
            const uint32_t wa = sbase + OFF_W + (uint32_t)(jj * W_STR + p0g * 2);
#pragma unroll
            for (int i = 0; i < 4; i++)
                STS32(wa + i * 4, pack_bf2(wv[2 * i], wv[2 * i + 1]));
        }
        __syncthreads();

        // ===== GEMM2 + fused epilogue 2 =====
        float s1 = 0.f, s2 = 0.f;
#pragma unroll
        for (int gq = 0; gq < 4; gq++) {
            s1 += sPart[gq * 64 + j1];
            s2 += sPart[gq * 64 + j1 + 8];
        }

        // a-frags (w) for both k16 steps, loaded once
        uint32_t aw[2][4];
#pragma unroll
        for (int ks = 0; ks < 2; ks++) {
            const uint32_t wh = sbase + OFF_W + wOffA + ks * 32;
            LDS32(aw[ks][0], wh);
            LDS32(aw[ks][1], wh + 8 * W_STR);
            LDS32(aw[ks][2], wh + 16);
            LDS32(aw[ks][3], wh + 8 * W_STR + 16);
        }

        const size_t c1 = (size_t)col0 + j1;
#pragma unroll 1
        for (int h = 0; h < 4; h++) {        // four 32-d slices of this half
            // preload epilogue Z values before the MMAs
            float zr[4][4];
#pragma unroll
            for (int nt = 0; nt < 4; nt++) {
                const int d0 = dh * 128 + h * 32 + nt * 8 + 2 * (lane & 3);
                const size_t o00 = (size_t)d0 * sN + c1;
                const size_t o01 = (size_t)(d0 + 1) * sN + c1;
                zr[nt][0] = ZPi[o00];
                zr[nt][1] = ZPi[o01];
                zr[nt][2] = ZPi[o00 + 8];
                zr[nt][3] = ZPi[o01 + 8];
            }

            float d2[4][4];
#pragma unroll
            for (int nt = 0; nt < 4; nt++)
#pragma unroll
                for (int q = 0; q < 4; q++) d2[nt][q] = 0.f;

#pragma unroll
            for (int ks = 0; ks < 2; ks++) {
#pragma unroll
                for (int ntp = 0; ntp < 2; ntp++) {
                    const int d0p = dh * 128 + h * 32 + ntp * 16;
                    const uint32_t la = (uint32_t)((ks * 16 + p_l) * U1_STR +
                                                   (d0p + dcol_l) * 2);
                    uint32_t b0, b1, b2, b3;
                    LDSM_T4(b0, b1, b2, b3, sbase + OFF_U1H + la);
                    MMA_BF16(d2[2 * ntp], aw[ks][0], aw[ks][1], aw[ks][2], aw[ks][3], b0, b1);
                    MMA_BF16(d2[2 * ntp + 1], aw[ks][0], aw[ks][1], aw[ks][2], aw[ks][3], b2, b3);
                }
            }

            // fused epilogue 2: out = z*s + D2 (32B-sector coalesced)
#pragma unroll
            for (int nt = 0; nt < 4; nt++) {
                const int d0 = dh * 128 + h * 32 + nt * 8 + 2 * (lane & 3);
                const size_t o00 = (size_t)d0 * sN + c1;
                const size_t o01 = (size_t)(d0 + 1) * sN + c1;
                out[o00] = fmaf(zr[nt][0], s1, d2[nt][0]);
                out[o01] = fmaf(zr[nt][1], s1, d2[nt][1]);
                out[o00 + 8] = fmaf(zr[nt][2], s2, d2[nt][2]);
                out[o01 + 8] = fmaf(zr[nt][3], s2, d2[nt][3]);
            }
        }
        __syncthreads();   // W/sPart/D1 dead before next tile's phase 1
    }
}

extern "C" void kernel_launch(void* const* d_in, const int* in_sizes, int n_in,
                              void* d_out, int out_size) {
    const float* ZPi   = (const float*)d_in[0];
    const float* U     = (const float*)d_in[1];
    const float* alpha = (const float*)d_in[2];
    float* out = (float*)d_out;

    const int N = in_sizes[0] / (DD + PP);
    const int ntiles = N / TILE;

    static int nsm = 0;
    if (nsm == 0) {
        cudaDeviceGetAttribute(&nsm, cudaDevAttrMultiProcessorCount, 0);
        cudaFuncSetAttribute(cclayer_mma5, cudaFuncAttributeMaxDynamicSharedMemorySize,
                             SMEM_BYTES);
    }
    int grid = 4 * nsm;
    if (grid > ntiles) grid = ntiles;
    cclayer_mma5<<<grid, THREADS, SMEM_BYTES>>>(ZPi, U, alpha, out, N, ntiles);
}

// round 12
// speedup vs baseline: 1.3833x; 1.0053x over previous
#include <cuda_runtime.h>
#include <cuda_bf16.h>
#include <cstdint>
#include <cstddef>

// CCLayer via HMMA bf16 (single precision level — no hi/lo split).
// TILE=64, 256 threads, 4 CTAs/SM.
//   D1[j,p] = Z_tile^T @ U ; w = (alpha - D1).*Pi ; s = colsum(Pi)
//   D2[j,d] = w @ U^T ; out[0:256] = z*s + D2 ; out[256:288] = Pi
#define DD 256
#define PP 32
#define TILE 64
#define THREADS 256

#define U1_STR 528           // U1[p][d] bf16 rows
#define D1_STR 132           // 33 words, gcd(33,32)=1 -> conflict-free epi reads
#define D1_KH  8448          // 64*132
#define W_STR  84            // W[j][p] bf16 rows

// ---- persistent smem (bytes) ----
#define OFF_A      0         // 256 rows x 128B (64 j bf16), XOR-swizzled  (32KB)
#define OFF_U1H    32768     // 32*528 = 16896
#define OFF_ALPHA  49664     // 32 f32
#define OFF_SPART  49792     // 4*64 f32 = 1024
#define SMEM_BYTES 50816

// ---- aliases inside A region (A dead after GEMM1) ----
#define OFF_D1     0         // 2*8448 = 16896
#define OFF_W      16896     // 64*84 = 5376, ends 22272 < 32768

#define MMA_BF16(d, a0, a1, a2, a3, b0, b1)                                  \
    asm volatile(                                                            \
        "mma.sync.aligned.m16n8k16.row.col.f32.bf16.bf16.f32 "               \
        "{%0,%1,%2,%3}, {%4,%5,%6,%7}, {%8,%9}, {%0,%1,%2,%3};"              \
        : "+f"(d[0]), "+f"(d[1]), "+f"(d[2]), "+f"(d[3])                     \
        : "r"(a0), "r"(a1), "r"(a2), "r"(a3), "r"(b0), "r"(b1))

#define LDSM_T4(r0, r1, r2, r3, addr)                                        \
    asm volatile(                                                            \
        "ldmatrix.sync.aligned.m8n8.x4.trans.shared.b16 {%0,%1,%2,%3}, [%4];"\
        : "=r"(r0), "=r"(r1), "=r"(r2), "=r"(r3) : "r"(addr))

#define LDS32(r, addr) \
    asm volatile("ld.shared.b32 %0, [%1];" : "=r"(r) : "r"(addr))
#define LDSF(r, addr) \
    asm volatile("ld.shared.f32 %0, [%1];" : "=f"(r) : "r"(addr))
#define STS32(addr, v) \
    asm volatile("st.shared.b32 [%0], %1;" :: "r"(addr), "r"(v) : "memory")
#define STSF(addr, v) \
    asm volatile("st.shared.f32 [%0], %1;" :: "r"(addr), "f"(v) : "memory")

__device__ __forceinline__ uint32_t pack_bf2(float a, float b) {
    return (uint32_t)__bfloat16_as_ushort(__float2bfloat16_rn(a)) |
           ((uint32_t)__bfloat16_as_ushort(__float2bfloat16_rn(b)) << 16);
}

__global__ __launch_bounds__(THREADS, 4)
void cclayer_mma5(const float* __restrict__ ZPi,
                  const float* __restrict__ U,
                  const float* __restrict__ alpha,
                  float* __restrict__ out,
                  int N, int ntiles) {
    extern __shared__ __align__(128) char smem[];
    uint32_t sbase;
    asm("{ .reg .u64 t; cvta.to.shared.u64 t, %1; cvt.u32.u64 %0, t; }"
        : "=r"(sbase) : "l"(smem));

    const int tid = threadIdx.x;
    const int warp = tid >> 5;
    const int lane = tid & 31;
    const size_t sN = (size_t)N;

    // ---- persistent: U1[p][d] bf16, alpha ----
    for (int i = tid; i < DD * PP; i += THREADS) {
        const int d = i >> 5, p = i & 31;
        *(uint16_t*)(smem + OFF_U1H + p * U1_STR + d * 2) =
            __bfloat16_as_ushort(__float2bfloat16_rn(U[i]));
    }
    if (tid < PP) ((float*)(smem + OFF_ALPHA))[tid] = alpha[tid];
    __syncthreads();

    const float* __restrict__ sAlpha = (const float*)(smem + OFF_ALPHA);
    float* __restrict__ sPart = (float*)(smem + OFF_SPART);

    // GEMM1 decode: warp = jh(4) + 4*kh(2)
    const int jh = warp & 3;
    const int kh = warp >> 2;
    const int krow_l = (lane & 7) + ((lane >> 4) & 1) * 8;
    const int jcolb = jh * 32 + ((lane >> 3) & 1) * 16;
    const uint32_t b1off = (uint32_t)((lane >> 2) * U1_STR + (lane & 3) * 4);
    // GEMM2 decode: warp = jblk(4) + 4*dh(2)
    const int jblk = (warp & 3) * 16;
    const int dh = warp >> 2;
    const uint32_t wOffA = (uint32_t)((jblk + (lane >> 2)) * W_STR + (lane & 3) * 4);
    const int p_l = (lane & 7) + ((lane >> 3) & 1) * 8;
    const int dcol_l = ((lane >> 4) & 1) * 8;
    const int j1 = jblk + (lane >> 2);
    // epi1 mapping: 4 p-groups x 64 j
    const int jj = tid & 63;
    const int pg = tid >> 6;             // 0..3, 8 p's each
    const int p0g = pg * 8;

    for (int t = blockIdx.x; t < ntiles; t += gridDim.x) {
        const int col0 = t * TILE;

        // ===== phase 1: Z tile -> A bf16 (swizzled) =====
#pragma unroll 4
        for (int i = 0; i < 32; i++) {
            const int d = warp * 32 + i;
            const float2 v = *(const float2*)(ZPi + (size_t)d * sN + col0 + 2 * lane);
            const uint32_t off = (uint32_t)(d * 128 + lane * 4) ^ (uint32_t)((d & 7) << 4);
            *(uint32_t*)(smem + OFF_A + off) = pack_bf2(v.x, v.y);
        }

        // ---- early Pi: regs + pass-through + partial s ----
        float piR[8];
        {
            float sacc = 0.f;
            const size_t c = (size_t)col0 + jj;
#pragma unroll
            for (int i = 0; i < 8; i++) {
                const size_t off = (size_t)(DD + p0g + i) * sN + c;
                piR[i] = ZPi[off];
                out[off] = piR[i];
                sacc += piR[i];
            }
            sPart[pg * 64 + jj] = sacc;
        }
        __syncthreads();

        // ===== GEMM1: D1[j,p] partials, k-split 2 =====
        float d1[4][4];
#pragma unroll
        for (int nt = 0; nt < 4; nt++)
#pragma unroll
            for (int q = 0; q < 4; q++) d1[nt][q] = 0.f;

#pragma unroll
        for (int ks = 0; ks < 8; ks++) {
            const int dbase = kh * 128 + ks * 16;
            const int d_l = dbase + krow_l;
            const uint32_t asw = (uint32_t)(d_l * 128 + jcolb) ^ (uint32_t)((d_l & 7) << 4);
            uint32_t a0, a1, a2, a3;
            LDSM_T4(a0, a1, a2, a3, sbase + OFF_A + asw);
            const uint32_t bb = sbase + OFF_U1H + b1off + dbase * 2;
#pragma unroll
            for (int nt = 0; nt < 4; nt++) {
                uint32_t b0, b1;
                LDS32(b0, bb + nt * 8 * U1_STR);
                LDS32(b1, bb + nt * 8 * U1_STR + 16);
                MMA_BF16(d1[nt], a0, a1, a2, a3, b0, b1);
            }
        }
        __syncthreads();   // all A reads done before aliased D1/W writes

        // ---- store D1 partials [kh][j][p] ----
        {
            const uint32_t base = sbase + OFF_D1 + kh * D1_KH;
            const int jr = jh * 16 + (lane >> 2);
#pragma unroll
            for (int nt = 0; nt < 4; nt++) {
                const int p = nt * 8 + 2 * (lane & 3);
                const uint32_t a0 = base + jr * D1_STR + p * 4;
                const uint32_t a1 = base + (jr + 8) * D1_STR + p * 4;
                STSF(a0, d1[nt][0]);
                STSF(a0 + 4, d1[nt][1]);
                STSF(a1, d1[nt][2]);
                STSF(a1 + 4, d1[nt][3]);
            }
        }
        __syncthreads();

        // ===== epilogue 1: w from D1 + reg Pi =====
        {
            const uint32_t db = sbase + OFF_D1 + jj * D1_STR;
            float wv[8];
#pragma unroll
            for (int i = 0; i < 8; i++) {
                const int p = p0g + i;
                float x0, x1;
                LDSF(x0, db + p * 4);
                LDSF(x1, db + D1_KH + p * 4);
                wv[i] = (sAlpha[p] - (x0 + x1)) * piR[i];
            }
            const uint32_t wa = sbase + OFF_W + (uint32_t)(jj * W_STR + p0g * 2);
#pragma unroll
            for (int i = 0; i < 4; i++)
                STS32(wa + i * 4, pack_bf2(wv[2 * i], wv[2 * i + 1]));
        }
        __syncthreads();

        // ===== GEMM2 + fused epilogue 2 =====
        float s1 = 0.f, s2 = 0.f;
#pragma unroll
        for (int gq = 0; gq < 4; gq++) {
            s1 += sPart[gq * 64 + j1];
            s2 += sPart[gq * 64 + j1 + 8];
        }

        // a-frags (w) for both k16 steps, loaded once
        uint32_t aw[2][4];
#pragma unroll
        for (int ks = 0; ks < 2; ks++) {
            const uint32_t wh = sbase + OFF_W + wOffA + ks * 32;
            LDS32(aw[ks][0], wh);
            LDS32(aw[ks][1], wh + 8 * W_STR);
            LDS32(aw[ks][2], wh + 16);
            LDS32(aw[ks][3], wh + 8 * W_STR + 16);
        }

        const size_t c1 = (size_t)col0 + j1;
#pragma unroll 1
        for (int h = 0; h < 4; h++) {        // four 32-d slices of this half
            // preload epilogue Z values before the MMAs
            float zr[4][4];
#pragma unroll
            for (int nt = 0; nt < 4; nt++) {
                const int d0 = dh * 128 + h * 32 + nt * 8 + 2 * (lane & 3);
                const size_t o00 = (size_t)d0 * sN + c1;
                const size_t o01 = (size_t)(d0 + 1) * sN + c1;
                zr[nt][0] = ZPi[o00];
                zr[nt][1] = ZPi[o01];
                zr[nt][2] = ZPi[o00 + 8];
                zr[nt][3] = ZPi[o01 + 8];
            }

            float d2[4][4];
#pragma unroll
            for (int nt = 0; nt < 4; nt++)
#pragma unroll
                for (int q = 0; q < 4; q++) d2[nt][q] = 0.f;

#pragma unroll
            for (int ks = 0; ks < 2; ks++) {
#pragma unroll
                for (int ntp = 0; ntp < 2; ntp++) {
                    const int d0p = dh * 128 + h * 32 + ntp * 16;
                    const uint32_t la = (uint32_t)((ks * 16 + p_l) * U1_STR +
                                                   (d0p + dcol_l) * 2);
                    uint32_t b0, b1, b2, b3;
                    LDSM_T4(b0, b1, b2, b3, sbase + OFF_U1H + la);
                    MMA_BF16(d2[2 * ntp], aw[ks][0], aw[ks][1], aw[ks][2], aw[ks][3], b0, b1);
                    MMA_BF16(d2[2 * ntp + 1], aw[ks][0], aw[ks][1], aw[ks][2], aw[ks][3], b2, b3);
                }
            }

            // fused epilogue 2: out = z*s + D2 (32B-sector coalesced)
#pragma unroll
            for (int nt = 0; nt < 4; nt++) {
                const int d0 = dh * 128 + h * 32 + nt * 8 + 2 * (lane & 3);
                const size_t o00 = (size_t)d0 * sN + c1;
                const size_t o01 = (size_t)(d0 + 1) * sN + c1;
                out[o00] = fmaf(zr[nt][0], s1, d2[nt][0]);
                out[o01] = fmaf(zr[nt][1], s1, d2[nt][1]);
                out[o00 + 8] = fmaf(zr[nt][2], s2, d2[nt][2]);
                out[o01 + 8] = fmaf(zr[nt][3], s2, d2[nt][3]);
            }
        }
        __syncthreads();   // W/sPart/D1 dead before next tile's phase 1
    }
}

extern "C" void kernel_launch(void* const* d_in, const int* in_sizes, int n_in,
                              void* d_out, int out_size) {
    const float* ZPi   = (const float*)d_in[0];
    const float* U     = (const float*)d_in[1];
    const float* alpha = (const float*)d_in[2];
    float* out = (float*)d_out;

    const int N = in_sizes[0] / (DD + PP);
    const int ntiles = N / TILE;

    static int nsm = 0;
    if (nsm == 0) {
        cudaDeviceGetAttribute(&nsm, cudaDevAttrMultiProcessorCount, 0);
        cudaFuncSetAttribute(cclayer_mma5, cudaFuncAttributeMaxDynamicSharedMemorySize,
                             SMEM_BYTES);
    }
    int grid = 4 * nsm;
    if (grid > ntiles) grid = ntiles;
    cclayer_mma5<<<grid, THREADS, SMEM_BYTES>>>(ZPi, U, alpha, out, N, ntiles);
}